// round 11
// baseline (speedup 1.0000x reference)
#include <cuda_runtime.h>
#include <cstdint>

// Binarize: x[4096, 8192] fp32, depth[3] -> out[4096, 3, 1024] float32,
// each output element = numeric value of the big-endian packed byte.
//
// R11: split L2-residency policy on the INPUT. L2=126MB; input=134MB;
// output=50MB. A 64MB input prefix is loaded with .cg (L2-resident across
// graph replays, like the output since R6); the remaining ~70MB streams with
// .cs (evict-first). Steady-state DRAM traffic/replay drops from ~142MB
// (all reads) to ~70-80MB; the resident prefix is served from L2.
// Resident set = 64 (prefix) + 50 (output) = 114MB < 126MB.
// Pack via float accumulation on the fma pipe (exact, sums of distinct
// powers of two <= 255). 8 consecutive floats/thread (32B lane stride,
// L1-optimal per R8's lesson).

#define COLS 8192
#define BPR  (COLS / 8)     // 1024 packed bytes (output floats) per row per plane

__device__ __forceinline__ float pack8f(const float4 u, const float4 v, float d)
{
    // Big-endian: element e has weight 2^(7-e). u = elems 0..3, v = 4..7.
    float acc = 0.0f;
    if (u.x > d) acc += 128.0f;
    if (u.y > d) acc += 64.0f;
    if (u.z > d) acc += 32.0f;
    if (u.w > d) acc += 16.0f;
    if (v.x > d) acc += 8.0f;
    if (v.y > d) acc += 4.0f;
    if (v.z > d) acc += 2.0f;
    if (v.w > d) acc += 1.0f;
    return acc;
}

__global__ __launch_bounds__(256) void binarize_kernel(
    const float* __restrict__ x,
    const float* __restrict__ depth,
    float* __restrict__ out,
    int nchunks,            // total 8-element chunks = n/8
    int pchunks)            // chunks loaded with .cg (L2-resident prefix)
{
    const float d0 = __ldg(depth + 0);
    const float d1 = __ldg(depth + 1);
    const float d2 = __ldg(depth + 2);

    const float4* __restrict__ x4 = reinterpret_cast<const float4*>(x);

    const int stride = gridDim.x * blockDim.x;
#pragma unroll 1
    for (int c = blockIdx.x * blockDim.x + threadIdx.x; c < nchunks; c += stride) {
        // Warp-uniform policy branch: prefix -> .cg (resident), rest -> .cs.
        float4 a, b;
        if (c < pchunks) {
            a = __ldcg(x4 + 2 * (size_t)c);
            b = __ldcg(x4 + 2 * (size_t)c + 1);
        } else {
            a = __ldcs(x4 + 2 * (size_t)c);
            b = __ldcs(x4 + 2 * (size_t)c + 1);
        }

        const float r0 = pack8f(a, b, d0);
        const float r1 = pack8f(a, b, d1);
        const float r2 = pack8f(a, b, d2);

        const int row = c >> 10;           // c / BPR
        const int t   = c & (BPR - 1);
        float* o = out + (size_t)row * (3 * BPR) + t;
        __stcg(o,           r0);
        __stcg(o + BPR,     r1);
        __stcg(o + 2 * BPR, r2);
    }
}

extern "C" void kernel_launch(void* const* d_in, const int* in_sizes, int n_in,
                              void* d_out, int out_size) {
    const float* x     = (const float*)d_in[0];
    const float* depth = (const float*)d_in[1];
    float*       out   = (float*)d_out;

    const int n       = in_sizes[0];   // 4096 * 8192
    const int nchunks = n / 8;

    // 64MB prefix kept L2-resident: 64MB / 32B per chunk = 2M chunks.
    int pchunks = (64 * 1024 * 1024) / 32;
    if (pchunks > nchunks) pchunks = nchunks;

    const int block = 256;
    int grid = 148 * 8;                // persistent: 8 blocks/SM
    const int max_grid = (nchunks + block - 1) / block;
    if (grid > max_grid) grid = max_grid;

    binarize_kernel<<<grid, block>>>(x, depth, out, nchunks, pchunks);
}